// round 11
// baseline (speedup 1.0000x reference)
#include <cuda_runtime.h>
#include <cuda_fp16.h>
#include <cstdint>

#define N_NODES 10000
#define N_EDGES 160000
#define IN_DIM  512
#define OUT_DIM 512
#define N_HOPS  3
#define LDC     (N_HOPS * OUT_DIM)   // 1536
#define VEC4    (IN_DIM / 4)

// ---------------- scratch (no allocations allowed) ----------------
__device__ __half g_f16[N_NODES * IN_DIM];    // features fp16 (GEMM A z=0, gather hop1)
__device__ __half g_h1h[N_NODES * IN_DIM];    // h1 fp16 (GEMM A z=1, gather hop2)
__device__ __half g_h2h[N_NODES * IN_DIM];    // h2 fp16 (GEMM A z=2)
__device__ __half g_wt16[N_HOPS * IN_DIM * OUT_DIM]; // Wt[z][n][k] fp16
__device__ int   g_counts[N_NODES];           // zero at load; re-zeroed by scatter each call
__device__ int   g_row_ptr[N_NODES + 1];
__device__ int   g_cursor[N_NODES];
__device__ int   g_csr_src[N_EDGES];
__device__ float g_csr_w[N_EDGES];

// ---------------- helpers ----------------
__device__ __forceinline__ uint32_t smem_u32(const void* p) {
    uint32_t a;
    asm("{ .reg .u64 t; cvta.to.shared.u64 t, %1; cvt.u32.u64 %0, t; }" : "=r"(a) : "l"(p));
    return a;
}
__device__ __forceinline__ void cp16(uint32_t saddr, const void* g) {
    asm volatile("cp.async.ca.shared.global [%0], [%1], 16;" :: "r"(saddr), "l"(g));
}
__device__ __forceinline__ void cp_commit() {
    asm volatile("cp.async.commit_group;" ::: "memory");
}
template <int N>
__device__ __forceinline__ void cp_wait() {
    asm volatile("cp.async.wait_group %0;" :: "n"(N) : "memory");
}
__device__ __forceinline__ void ldsm_x4(uint32_t* r, uint32_t addr) {
    asm volatile("ldmatrix.sync.aligned.m8n8.x4.shared.b16 {%0,%1,%2,%3}, [%4];"
                 : "=r"(r[0]), "=r"(r[1]), "=r"(r[2]), "=r"(r[3]) : "r"(addr));
}
__device__ __forceinline__ void mma16816h(float* c, const uint32_t* a, const uint32_t* b) {
    asm volatile(
        "mma.sync.aligned.m16n8k16.row.col.f32.f16.f16.f32 "
        "{%0,%1,%2,%3}, {%4,%5,%6,%7}, {%8,%9}, {%0,%1,%2,%3};"
        : "+f"(c[0]), "+f"(c[1]), "+f"(c[2]), "+f"(c[3])
        : "r"(a[0]), "r"(a[1]), "r"(a[2]), "r"(a[3]), "r"(b[0]), "r"(b[1]));
}

// ---------------- fused prep: feat->fp16 + edge hist + W transpose ----------------
// blocks [0, 5000): feature convert + hist; blocks [5000, 5768): 32x32 W-transpose tiles
#define PREP_FEAT_BLOCKS 5000                      // 5000*256 == N_NODES*VEC4
#define PREP_WT_BLOCKS   (16 * 16 * N_HOPS)        // 768
__global__ void prep_kernel(const float* __restrict__ feat, const float* __restrict__ W,
                            const int* __restrict__ dst) {
    __shared__ float tbuf[32][33];
    int b = blockIdx.x;
    if (b < PREP_FEAT_BLOCKS) {
        int i = b * 256 + threadIdx.x;
        float4 r = reinterpret_cast<const float4*>(feat)[i];
        reinterpret_cast<__half2*>(g_f16)[i * 2 + 0] = __floats2half2_rn(r.x, r.y);
        reinterpret_cast<__half2*>(g_f16)[i * 2 + 1] = __floats2half2_rn(r.z, r.w);
        if (i < N_EDGES) atomicAdd(&g_counts[dst[i]], 1);
    } else {
        int id = b - PREP_FEAT_BLOCKS;
        int z = id >> 8;                  // 256 tiles per z
        int tile = id & 255;
        int k0 = (tile & 15) * 32, n0 = (tile >> 4) * 32;
        int tx = threadIdx.x & 31, ty = threadIdx.x >> 5;   // (32, 8)
        const float* Wz = W + (size_t)z * IN_DIM * OUT_DIM;
#pragma unroll
        for (int r = 0; r < 4; r++)
            tbuf[ty + 8 * r][tx] = Wz[(size_t)(k0 + ty + 8 * r) * OUT_DIM + n0 + tx];
        __syncthreads();
        __half* Wt = g_wt16 + (size_t)z * IN_DIM * OUT_DIM;
#pragma unroll
        for (int r = 0; r < 4; r++)
            Wt[(size_t)(n0 + ty + 8 * r) * IN_DIM + k0 + tx] = __float2half(tbuf[tx][ty + 8 * r]);
    }
}

// ---------------- CSR build ----------------
__global__ void scan_kernel() {
    const int T = 1024, PER = 10;
    __shared__ int warp_tot[32];
    int t = threadIdx.x;
    int lane = t & 31, wd = t >> 5;
    int local[PER];
    int s = 0;
#pragma unroll
    for (int j = 0; j < PER; j++) {
        int idx = t * PER + j;
        int c = (idx < N_NODES) ? g_counts[idx] : 0;
        local[j] = s; s += c;
    }
    int tot = s;
    int inc = s;
#pragma unroll
    for (int off = 1; off < 32; off <<= 1) {
        int v = __shfl_up_sync(0xFFFFFFFF, inc, off);
        if (lane >= off) inc += v;
    }
    if (lane == 31) warp_tot[wd] = inc;
    __syncthreads();
    if (wd == 0) {
        int iv = warp_tot[lane];
#pragma unroll
        for (int off = 1; off < 32; off <<= 1) {
            int u = __shfl_up_sync(0xFFFFFFFF, iv, off);
            if (lane >= off) iv += u;
        }
        warp_tot[lane] = iv;
    }
    __syncthreads();
    int base = (wd > 0 ? warp_tot[wd - 1] : 0) + (inc - tot);
#pragma unroll
    for (int j = 0; j < PER; j++) {
        int idx = t * PER + j;
        if (idx < N_NODES) {
            int v = base + local[j];
            g_row_ptr[idx] = v;
            g_cursor[idx]  = v;
        }
    }
    if (t == T - 1) g_row_ptr[N_NODES] = base + tot;
}

// scatter (2 edges per thread for MLP) + re-zero counts
__global__ void scatter_kernel(const int* __restrict__ src, const int* __restrict__ dst,
                               const float* __restrict__ w) {
    int i = blockIdx.x * blockDim.x + threadIdx.x;
    int e0 = i * 2, e1 = i * 2 + 1;
    if (e0 < N_EDGES) {
        int d0 = dst[e0];
        int s0 = src[e0];
        float w0 = w[e0];
        int d1 = -1, s1 = 0; float w1 = 0.f;
        if (e1 < N_EDGES) { d1 = dst[e1]; s1 = src[e1]; w1 = w[e1]; }
        int p0 = atomicAdd(&g_cursor[d0], 1);
        g_csr_src[p0] = s0;
        g_csr_w[p0]   = w0;
        if (d1 >= 0) {
            int p1 = atomicAdd(&g_cursor[d1], 1);
            g_csr_src[p1] = s1;
            g_csr_w[p1]   = w1;
        }
    }
    if (i < N_NODES) g_counts[i] = 0;
}

// ---------------- SpMM hop (fp16 gather, fp32 accumulate, fp16 store) ----------------
// 64 threads per node; thread t owns 8 halves (16B) at column t*8
__global__ __launch_bounds__(64) void spmm_kernel(const float* __restrict__ D_norm, int hop) {
    const __half* __restrict__ h_in  = (hop == 1) ? g_f16 : g_h1h;
    __half* __restrict__       h_out = (hop == 1) ? g_h1h : g_h2h;
    int n = blockIdx.x;
    int t = threadIdx.x;   // 0..63
    int beg = g_row_ptr[n];
    int end = g_row_ptr[n + 1];

    __shared__ int2 s_ew[64];   // (src, w bits)

    float acc[8];
#pragma unroll
    for (int q = 0; q < 8; q++) acc[q] = 0.f;

    for (int base = beg; base < end; base += 64) {
        int cnt = min(64, end - base);
        if (t < cnt)
            s_ew[t] = make_int2(g_csr_src[base + t], __float_as_int(g_csr_w[base + t]));
        __syncthreads();
#pragma unroll 2
        for (int i = 0; i < cnt; i++) {
            int2 ew = s_ew[i];
            uint4 raw = reinterpret_cast<const uint4*>(h_in + (size_t)ew.x * IN_DIM)[t];
            float w = __int_as_float(ew.y);
            const __half2* ph = reinterpret_cast<const __half2*>(&raw);
#pragma unroll
            for (int q = 0; q < 4; q++) {
                float2 f = __half22float2(ph[q]);
                acc[2 * q + 0] += f.x * w;
                acc[2 * q + 1] += f.y * w;
            }
        }
        __syncthreads();
    }
    float d = D_norm[n];
    __half2 o[4];
#pragma unroll
    for (int q = 0; q < 4; q++)
        o[q] = __floats2half2_rn(acc[2 * q] * d, acc[2 * q + 1] * d);
    reinterpret_cast<uint4*>(h_out + (size_t)n * IN_DIM)[t] = *reinterpret_cast<uint4*>(o);
}

// ---------------- fp16 mma GEMM + bias + relu, BK=64, 3-stage cp.async pipeline ----------------
// Row = 128B data + 16B pad = 144B (9 granules; 9 mod 8 = 1 -> conflict-free ldmatrix)
#define TROW_B    144
#define TILE_B    (128 * TROW_B)     // 18432
#define STAGE_B   (2 * TILE_B)       // 36864: A, B
#define KCHUNKS   8                  // 512 / 64
#define NSTAGE    3
#define GEMM_SMEM (NSTAGE * STAGE_B) // 110592

__global__ void __launch_bounds__(256, 2) gemm_mma_kernel(const float* __restrict__ bias,
                                                          float* __restrict__ out, int z_off) {
    extern __shared__ char sm[];

    const int tid = threadIdx.x;
    const int wid = tid >> 5, lane = tid & 31;
    const int warp_m = wid & 1, warp_n = wid >> 1;
    const int nt = blockIdx.x, mt = blockIdx.y, z = blockIdx.z + z_off;
    const int m_base = mt * 128, n_base = nt * 128;

    const __half* A = (z == 0) ? g_f16 : (z == 1) ? g_h1h : g_h2h;
    const __half* B = g_wt16 + (size_t)z * IN_DIM * OUT_DIM;

    const uint32_t s_base = smem_u32(sm);

    // 1024 16B-chunks per tile (128 rows x 8), 256 threads -> 4 chunks each per tile
    const int rr[4] = { tid >> 3, (tid + 256) >> 3, (tid + 512) >> 3, (tid + 768) >> 3 };
    const int jj[4] = { tid & 7, (tid + 256) & 7, (tid + 512) & 7, (tid + 768) & 7 };
    int amr[4], bnr[4];
#pragma unroll
    for (int q = 0; q < 4; q++) {
        amr[q] = min(m_base + rr[q], N_NODES - 1);
        bnr[q] = n_base + rr[q];
    }

    auto issue_stage = [&](int s, int kc) {
        uint32_t st = s_base + s * STAGE_B;
        int kh = kc * 64;   // halves
#pragma unroll
        for (int q = 0; q < 4; q++) {
            cp16(st + 0 * TILE_B + rr[q] * TROW_B + jj[q] * 16, A + (size_t)amr[q] * IN_DIM + kh + jj[q] * 8);
            cp16(st + 1 * TILE_B + rr[q] * TROW_B + jj[q] * 16, B + (size_t)bnr[q] * IN_DIM + kh + jj[q] * 8);
        }
    };

    float acc[4][4][4];
#pragma unroll
    for (int i = 0; i < 4; i++)
#pragma unroll
        for (int j = 0; j < 4; j++)
#pragma unroll
            for (int q = 0; q < 4; q++) acc[i][j][q] = 0.f;

    const int a_row = warp_m * 64 + (lane & 15);
    const int a_kb  = (lane >> 4) * 16;
    const int b_row = warp_n * 32 + (lane & 7) + ((lane >> 4) << 3);
    const int b_kb  = ((lane >> 3) & 1) * 16;

    issue_stage(0, 0); cp_commit();
    issue_stage(1, 1); cp_commit();

    int stage = 0;
    for (int kc = 0; kc < KCHUNKS; kc++) {
        cp_wait<1>();
        __syncthreads();

        if (kc + 2 < KCHUNKS) {
            int s2 = stage + 2; if (s2 >= NSTAGE) s2 -= NSTAGE;
            issue_stage(s2, kc + 2);
        }
        cp_commit();   // possibly-empty group keeps wait<1> semantics uniform

        uint32_t st = s_base + stage * STAGE_B;
#pragma unroll
        for (int kk = 0; kk < 4; kk++) {
            int kb = kk * 32;   // 16 halves
            uint32_t af[4][4];
#pragma unroll
            for (int i = 0; i < 4; i++)
                ldsm_x4(af[i], st + 0 * TILE_B + (a_row + i * 16) * TROW_B + a_kb + kb);
            uint32_t bf[4][2];
#pragma unroll
            for (int jp = 0; jp < 2; jp++) {
                uint32_t r[4];
                ldsm_x4(r, st + 1 * TILE_B + (b_row + jp * 16) * TROW_B + b_kb + kb);
                bf[jp * 2][0] = r[0];     bf[jp * 2][1] = r[1];
                bf[jp * 2 + 1][0] = r[2]; bf[jp * 2 + 1][1] = r[3];
            }
#pragma unroll
            for (int i = 0; i < 4; i++)
#pragma unroll
                for (int j = 0; j < 4; j++)
                    mma16816h(acc[i][j], af[i], bf[j]);
        }
        if (++stage >= NSTAGE) stage = 0;
    }

    const float* bz = bias + z * OUT_DIM;
#pragma unroll
    for (int i = 0; i < 4; i++) {
        int row0 = m_base + warp_m * 64 + i * 16 + (lane >> 2);
#pragma unroll
        for (int j = 0; j < 4; j++) {
            int col = n_base + warp_n * 32 + j * 8 + (lane & 3) * 2;
            float b0 = bz[col], b1 = bz[col + 1];
            if (row0 < N_NODES) {
                float2 v;
                v.x = fmaxf(acc[i][j][0] + b0, 0.f);
                v.y = fmaxf(acc[i][j][1] + b1, 0.f);
                *(float2*)(out + (size_t)row0 * LDC + z * OUT_DIM + col) = v;
            }
            int row1 = row0 + 8;
            if (row1 < N_NODES) {
                float2 v;
                v.x = fmaxf(acc[i][j][2] + b0, 0.f);
                v.y = fmaxf(acc[i][j][3] + b1, 0.f);
                *(float2*)(out + (size_t)row1 * LDC + z * OUT_DIM + col) = v;
            }
        }
    }
}

// ---------------- launch ----------------
extern "C" void kernel_launch(void* const* d_in, const int* in_sizes, int n_in,
                              void* d_out, int out_size) {
    const float* features = (const float*)d_in[0];
    const float* D_norm   = (const float*)d_in[1];
    const float* edge_w   = (const float*)d_in[2];
    const float* W        = (const float*)d_in[3];
    const float* b        = (const float*)d_in[4];
    const int*   src      = (const int*)d_in[5];
    const int*   dst      = (const int*)d_in[6];
    float* out = (float*)d_out;

    static_assert(GEMM_SMEM <= 113 * 1024, "smem for 2 CTA/SM");
    cudaFuncSetAttribute(gemm_mma_kernel, cudaFuncAttributeMaxDynamicSharedMemorySize, GEMM_SMEM);

    cudaEvent_t evA, evB;
    cudaEventCreateWithFlags(&evA, cudaEventDisableTiming);
    cudaEventCreateWithFlags(&evB, cudaEventDisableTiming);

    // main chain: prep(+wtrans) -> scan -> scatter -> [fork z0] -> spmm x2 -> gemm z12 -> join
    prep_kernel<<<PREP_FEAT_BLOCKS + PREP_WT_BLOCKS, 256>>>(features, W, dst);   // 1
    scan_kernel<<<1, 1024>>>();                                                  // 2
    scatter_kernel<<<(N_EDGES / 2 + 255) / 256, 256>>>(src, dst, edge_w);        // 3

    // fork AFTER scatter: gemm z=0 overlaps only the SpMM hops (scan/scatter run alone)
    cudaEventRecord(evA, 0);
    cudaStreamWaitEvent(cudaStreamPerThread, evA, 0);
    dim3 g0(OUT_DIM / 128, (N_NODES + 127) / 128, 1);
    gemm_mma_kernel<<<g0, 256, GEMM_SMEM, cudaStreamPerThread>>>(b, out, 0);     // 4
    cudaEventRecord(evB, cudaStreamPerThread);

    spmm_kernel<<<N_NODES, 64>>>(D_norm, 1);                                     // 5
    spmm_kernel<<<N_NODES, 64>>>(D_norm, 2);                                     // 6
    dim3 g12(OUT_DIM / 128, (N_NODES + 127) / 128, 2);
    gemm_mma_kernel<<<g12, 256, GEMM_SMEM>>>(b, out, 1);                         // 7

    cudaStreamWaitEvent(0, evB, 0);

    cudaEventDestroy(evA);
    cudaEventDestroy(evB);
}

// round 12
// speedup vs baseline: 1.0677x; 1.0677x over previous
#include <cuda_runtime.h>
#include <cuda_fp16.h>
#include <cstdint>

#define N_NODES 10000
#define N_EDGES 160000
#define IN_DIM  512
#define OUT_DIM 512
#define N_HOPS  3
#define LDC     (N_HOPS * OUT_DIM)   // 1536
#define VEC4    (IN_DIM / 4)

// ---------------- scratch (no allocations allowed) ----------------
__device__ __half g_f16[N_NODES * IN_DIM];    // features fp16 (GEMM A z=0, gather hop1)
__device__ __half g_h1h[N_NODES * IN_DIM];    // h1 fp16 (GEMM A z=1, gather hop2)
__device__ __half g_h2h[N_NODES * IN_DIM];    // h2 fp16 (GEMM A z=2)
__device__ __half g_wt16[N_HOPS * IN_DIM * OUT_DIM]; // Wt[z][n][k] fp16
__device__ int   g_counts[N_NODES];           // zero at load; re-zeroed by scatter each call
__device__ int   g_row_ptr[N_NODES + 1];
__device__ int   g_cursor[N_NODES];
__device__ int   g_csr_src[N_EDGES];
__device__ float g_csr_w[N_EDGES];

// ---------------- helpers ----------------
__device__ __forceinline__ uint32_t smem_u32(const void* p) {
    uint32_t a;
    asm("{ .reg .u64 t; cvta.to.shared.u64 t, %1; cvt.u32.u64 %0, t; }" : "=r"(a) : "l"(p));
    return a;
}
__device__ __forceinline__ void cp16(uint32_t saddr, const void* g) {
    asm volatile("cp.async.ca.shared.global [%0], [%1], 16;" :: "r"(saddr), "l"(g));
}
__device__ __forceinline__ void cp_commit() {
    asm volatile("cp.async.commit_group;" ::: "memory");
}
template <int N>
__device__ __forceinline__ void cp_wait() {
    asm volatile("cp.async.wait_group %0;" :: "n"(N) : "memory");
}
__device__ __forceinline__ void ldsm_x4(uint32_t* r, uint32_t addr) {
    asm volatile("ldmatrix.sync.aligned.m8n8.x4.shared.b16 {%0,%1,%2,%3}, [%4];"
                 : "=r"(r[0]), "=r"(r[1]), "=r"(r[2]), "=r"(r[3]) : "r"(addr));
}
__device__ __forceinline__ void mma16816h(float* c, const uint32_t* a, const uint32_t* b) {
    asm volatile(
        "mma.sync.aligned.m16n8k16.row.col.f32.f16.f16.f32 "
        "{%0,%1,%2,%3}, {%4,%5,%6,%7}, {%8,%9}, {%0,%1,%2,%3};"
        : "+f"(c[0]), "+f"(c[1]), "+f"(c[2]), "+f"(c[3])
        : "r"(a[0]), "r"(a[1]), "r"(a[2]), "r"(a[3]), "r"(b[0]), "r"(b[1]));
}

// ---------------- fused prep: feat->fp16 + edge hist + W transpose ----------------
// blocks [0, 5000): feature convert + hist; blocks [5000, 5768): 32x32 W-transpose tiles
#define PREP_FEAT_BLOCKS 5000                      // 5000*256 == N_NODES*VEC4
#define PREP_WT_BLOCKS   (16 * 16 * N_HOPS)        // 768
__global__ void prep_kernel(const float* __restrict__ feat, const float* __restrict__ W,
                            const int* __restrict__ dst) {
    __shared__ float tbuf[32][33];
    int b = blockIdx.x;
    if (b < PREP_FEAT_BLOCKS) {
        int i = b * 256 + threadIdx.x;
        float4 r = reinterpret_cast<const float4*>(feat)[i];
        reinterpret_cast<__half2*>(g_f16)[i * 2 + 0] = __floats2half2_rn(r.x, r.y);
        reinterpret_cast<__half2*>(g_f16)[i * 2 + 1] = __floats2half2_rn(r.z, r.w);
        if (i < N_EDGES) atomicAdd(&g_counts[dst[i]], 1);
    } else {
        int id = b - PREP_FEAT_BLOCKS;
        int z = id >> 8;                  // 256 tiles per z
        int tile = id & 255;
        int k0 = (tile & 15) * 32, n0 = (tile >> 4) * 32;
        int tx = threadIdx.x & 31, ty = threadIdx.x >> 5;   // (32, 8)
        const float* Wz = W + (size_t)z * IN_DIM * OUT_DIM;
#pragma unroll
        for (int r = 0; r < 4; r++)
            tbuf[ty + 8 * r][tx] = Wz[(size_t)(k0 + ty + 8 * r) * OUT_DIM + n0 + tx];
        __syncthreads();
        __half* Wt = g_wt16 + (size_t)z * IN_DIM * OUT_DIM;
#pragma unroll
        for (int r = 0; r < 4; r++)
            Wt[(size_t)(n0 + ty + 8 * r) * IN_DIM + k0 + tx] = __float2half(tbuf[tx][ty + 8 * r]);
    }
}

// ---------------- CSR build ----------------
__global__ void scan_kernel() {
    const int T = 1024, PER = 10;
    __shared__ int warp_tot[32];
    int t = threadIdx.x;
    int lane = t & 31, wd = t >> 5;
    int local[PER];
    int s = 0;
#pragma unroll
    for (int j = 0; j < PER; j++) {
        int idx = t * PER + j;
        int c = (idx < N_NODES) ? g_counts[idx] : 0;
        local[j] = s; s += c;
    }
    int tot = s;
    int inc = s;
#pragma unroll
    for (int off = 1; off < 32; off <<= 1) {
        int v = __shfl_up_sync(0xFFFFFFFF, inc, off);
        if (lane >= off) inc += v;
    }
    if (lane == 31) warp_tot[wd] = inc;
    __syncthreads();
    if (wd == 0) {
        int iv = warp_tot[lane];
#pragma unroll
        for (int off = 1; off < 32; off <<= 1) {
            int u = __shfl_up_sync(0xFFFFFFFF, iv, off);
            if (lane >= off) iv += u;
        }
        warp_tot[lane] = iv;
    }
    __syncthreads();
    int base = (wd > 0 ? warp_tot[wd - 1] : 0) + (inc - tot);
#pragma unroll
    for (int j = 0; j < PER; j++) {
        int idx = t * PER + j;
        if (idx < N_NODES) {
            int v = base + local[j];
            g_row_ptr[idx] = v;
            g_cursor[idx]  = v;
        }
    }
    if (t == T - 1) g_row_ptr[N_NODES] = base + tot;
}

// scatter (4 edges per thread for MLP) + re-zero counts
__global__ void scatter_kernel(const int* __restrict__ src, const int* __restrict__ dst,
                               const float* __restrict__ w) {
    int i = blockIdx.x * blockDim.x + threadIdx.x;
    int d[4], sv[4];
    float wv[4];
    int n_e = 0;
#pragma unroll
    for (int q = 0; q < 4; q++) {
        int e = i * 4 + q;
        if (e < N_EDGES) {
            d[q]  = dst[e];
            sv[q] = src[e];
            wv[q] = w[e];
            n_e = q + 1;
        }
    }
    int p[4];
#pragma unroll
    for (int q = 0; q < 4; q++)
        if (q < n_e) p[q] = atomicAdd(&g_cursor[d[q]], 1);
#pragma unroll
    for (int q = 0; q < 4; q++)
        if (q < n_e) { g_csr_src[p[q]] = sv[q]; g_csr_w[p[q]] = wv[q]; }
    if (i < N_NODES) g_counts[i] = 0;
}

// ---------------- SpMM hop (fp16 gather, fp32 accumulate, fp16 store) ----------------
// 64 threads per node; thread t owns 8 halves (16B) at column t*8
__global__ __launch_bounds__(64) void spmm_kernel(const float* __restrict__ D_norm, int hop) {
    const __half* __restrict__ h_in  = (hop == 1) ? g_f16 : g_h1h;
    __half* __restrict__       h_out = (hop == 1) ? g_h1h : g_h2h;
    int n = blockIdx.x;
    int t = threadIdx.x;   // 0..63
    int beg = g_row_ptr[n];
    int end = g_row_ptr[n + 1];
    float d = D_norm[n];

    __shared__ int2 s_ew[64];   // (src, w bits)

    float acc[8];
#pragma unroll
    for (int q = 0; q < 8; q++) acc[q] = 0.f;

    for (int base = beg; base < end; base += 64) {
        int cnt = min(64, end - base);
        if (t < cnt)
            s_ew[t] = make_int2(g_csr_src[base + t], __float_as_int(g_csr_w[base + t]));
        __syncthreads();
#pragma unroll 2
        for (int i = 0; i < cnt; i++) {
            int2 ew = s_ew[i];
            uint4 raw = reinterpret_cast<const uint4*>(h_in + (size_t)ew.x * IN_DIM)[t];
            float w = __int_as_float(ew.y);
            const __half2* ph = reinterpret_cast<const __half2*>(&raw);
#pragma unroll
            for (int q = 0; q < 4; q++) {
                float2 f = __half22float2(ph[q]);
                acc[2 * q + 0] += f.x * w;
                acc[2 * q + 1] += f.y * w;
            }
        }
        __syncthreads();
    }
    __half2 o[4];
#pragma unroll
    for (int q = 0; q < 4; q++)
        o[q] = __floats2half2_rn(acc[2 * q] * d, acc[2 * q + 1] * d);
    reinterpret_cast<uint4*>(h_out + (size_t)n * IN_DIM)[t] = *reinterpret_cast<uint4*>(o);
}

// ---------------- fp16 mma GEMM + bias + relu, BK=64, 3-stage cp.async pipeline ----------------
// Row = 128B data + 16B pad = 144B (9 granules; 9 mod 8 = 1 -> conflict-free ldmatrix)
#define TROW_B    144
#define TILE_B    (128 * TROW_B)     // 18432
#define STAGE_B   (2 * TILE_B)       // 36864: A, B
#define KCHUNKS   8                  // 512 / 64
#define NSTAGE    3
#define GEMM_SMEM (NSTAGE * STAGE_B) // 110592

__global__ void __launch_bounds__(256, 2) gemm_mma_kernel(const float* __restrict__ bias,
                                                          float* __restrict__ out) {
    extern __shared__ char sm[];

    const int tid = threadIdx.x;
    const int wid = tid >> 5, lane = tid & 31;
    const int warp_m = wid & 1, warp_n = wid >> 1;
    const int nt = blockIdx.x, mt = blockIdx.y, z = blockIdx.z;
    const int m_base = mt * 128, n_base = nt * 128;

    const __half* A = (z == 0) ? g_f16 : (z == 1) ? g_h1h : g_h2h;
    const __half* B = g_wt16 + (size_t)z * IN_DIM * OUT_DIM;

    const uint32_t s_base = smem_u32(sm);

    // 1024 16B-chunks per tile (128 rows x 8), 256 threads -> 4 chunks each per tile
    const int rr[4] = { tid >> 3, (tid + 256) >> 3, (tid + 512) >> 3, (tid + 768) >> 3 };
    const int jj[4] = { tid & 7, (tid + 256) & 7, (tid + 512) & 7, (tid + 768) & 7 };
    int amr[4], bnr[4];
#pragma unroll
    for (int q = 0; q < 4; q++) {
        amr[q] = min(m_base + rr[q], N_NODES - 1);
        bnr[q] = n_base + rr[q];
    }

    auto issue_stage = [&](int s, int kc) {
        uint32_t st = s_base + s * STAGE_B;
        int kh = kc * 64;   // halves
#pragma unroll
        for (int q = 0; q < 4; q++) {
            cp16(st + 0 * TILE_B + rr[q] * TROW_B + jj[q] * 16, A + (size_t)amr[q] * IN_DIM + kh + jj[q] * 8);
            cp16(st + 1 * TILE_B + rr[q] * TROW_B + jj[q] * 16, B + (size_t)bnr[q] * IN_DIM + kh + jj[q] * 8);
        }
    };

    float acc[4][4][4];
#pragma unroll
    for (int i = 0; i < 4; i++)
#pragma unroll
        for (int j = 0; j < 4; j++)
#pragma unroll
            for (int q = 0; q < 4; q++) acc[i][j][q] = 0.f;

    const int a_row = warp_m * 64 + (lane & 15);
    const int a_kb  = (lane >> 4) * 16;
    const int b_row = warp_n * 32 + (lane & 7) + ((lane >> 4) << 3);
    const int b_kb  = ((lane >> 3) & 1) * 16;

    issue_stage(0, 0); cp_commit();
    issue_stage(1, 1); cp_commit();

    int stage = 0;
    for (int kc = 0; kc < KCHUNKS; kc++) {
        cp_wait<1>();
        __syncthreads();

        if (kc + 2 < KCHUNKS) {
            int s2 = stage + 2; if (s2 >= NSTAGE) s2 -= NSTAGE;
            issue_stage(s2, kc + 2);
        }
        cp_commit();   // possibly-empty group keeps wait<1> semantics uniform

        uint32_t st = s_base + stage * STAGE_B;
#pragma unroll
        for (int kk = 0; kk < 4; kk++) {
            int kb = kk * 32;   // 16 halves
            uint32_t af[4][4];
#pragma unroll
            for (int i = 0; i < 4; i++)
                ldsm_x4(af[i], st + 0 * TILE_B + (a_row + i * 16) * TROW_B + a_kb + kb);
            uint32_t bf[4][2];
#pragma unroll
            for (int jp = 0; jp < 2; jp++) {
                uint32_t r[4];
                ldsm_x4(r, st + 1 * TILE_B + (b_row + jp * 16) * TROW_B + b_kb + kb);
                bf[jp * 2][0] = r[0];     bf[jp * 2][1] = r[1];
                bf[jp * 2 + 1][0] = r[2]; bf[jp * 2 + 1][1] = r[3];
            }
#pragma unroll
            for (int i = 0; i < 4; i++)
#pragma unroll
                for (int j = 0; j < 4; j++)
                    mma16816h(acc[i][j], af[i], bf[j]);
        }
        if (++stage >= NSTAGE) stage = 0;
    }

    const float* bz = bias + z * OUT_DIM;
#pragma unroll
    for (int i = 0; i < 4; i++) {
        int row0 = m_base + warp_m * 64 + i * 16 + (lane >> 2);
#pragma unroll
        for (int j = 0; j < 4; j++) {
            int col = n_base + warp_n * 32 + j * 8 + (lane & 3) * 2;
            float b0 = bz[col], b1 = bz[col + 1];
            if (row0 < N_NODES) {
                float2 v;
                v.x = fmaxf(acc[i][j][0] + b0, 0.f);
                v.y = fmaxf(acc[i][j][1] + b1, 0.f);
                *(float2*)(out + (size_t)row0 * LDC + z * OUT_DIM + col) = v;
            }
            int row1 = row0 + 8;
            if (row1 < N_NODES) {
                float2 v;
                v.x = fmaxf(acc[i][j][2] + b0, 0.f);
                v.y = fmaxf(acc[i][j][3] + b1, 0.f);
                *(float2*)(out + (size_t)row1 * LDC + z * OUT_DIM + col) = v;
            }
        }
    }
}

// ---------------- launch ----------------
extern "C" void kernel_launch(void* const* d_in, const int* in_sizes, int n_in,
                              void* d_out, int out_size) {
    const float* features = (const float*)d_in[0];
    const float* D_norm   = (const float*)d_in[1];
    const float* edge_w   = (const float*)d_in[2];
    const float* W        = (const float*)d_in[3];
    const float* b        = (const float*)d_in[4];
    const int*   src      = (const int*)d_in[5];
    const int*   dst      = (const int*)d_in[6];
    float* out = (float*)d_out;

    static_assert(GEMM_SMEM <= 113 * 1024, "smem for 2 CTA/SM");
    cudaFuncSetAttribute(gemm_mma_kernel, cudaFuncAttributeMaxDynamicSharedMemorySize, GEMM_SMEM);

    // serial chain, single merged GEMM launch (verified best structure)
    prep_kernel<<<PREP_FEAT_BLOCKS + PREP_WT_BLOCKS, 256>>>(features, W, dst);   // 1
    scan_kernel<<<1, 1024>>>();                                                  // 2
    scatter_kernel<<<(N_EDGES / 4 + 255) / 256, 256>>>(src, dst, edge_w);        // 3
    spmm_kernel<<<N_NODES, 64>>>(D_norm, 1);                                     // 4
    spmm_kernel<<<N_NODES, 64>>>(D_norm, 2);                                     // 5
    dim3 ggrid(OUT_DIM / 128, (N_NODES + 127) / 128, N_HOPS);
    gemm_mma_kernel<<<ggrid, 256, GEMM_SMEM>>>(b, out);                          // 6
}

// round 13
// speedup vs baseline: 1.1045x; 1.0345x over previous
#include <cuda_runtime.h>
#include <cuda_fp16.h>
#include <cstdint>

#define N_NODES 10000
#define N_EDGES 160000
#define IN_DIM  512
#define OUT_DIM 512
#define N_HOPS  3
#define LDC     (N_HOPS * OUT_DIM)   // 1536
#define VEC4    (IN_DIM / 4)

// ---------------- scratch (no allocations allowed) ----------------
__device__ __half g_f16[N_NODES * IN_DIM];    // features fp16 (GEMM A z=0, gather hop1)
__device__ __half g_h1h[N_NODES * IN_DIM];    // h1 fp16 (GEMM A z=1, gather hop2)
__device__ __half g_h2h[N_NODES * IN_DIM];    // h2 fp16 (GEMM A z=2)
__device__ __half g_wt16[N_HOPS * IN_DIM * OUT_DIM]; // Wt[z][n][k] fp16
__device__ int   g_counts[N_NODES];           // zero at load; re-zeroed by scatter each call
__device__ int   g_row_ptr[N_NODES + 1];
__device__ int   g_cursor[N_NODES];
__device__ int   g_csr_src[N_EDGES];
__device__ float g_csr_w[N_EDGES];

// ---------------- helpers ----------------
__device__ __forceinline__ uint32_t smem_u32(const void* p) {
    uint32_t a;
    asm("{ .reg .u64 t; cvta.to.shared.u64 t, %1; cvt.u32.u64 %0, t; }" : "=r"(a) : "l"(p));
    return a;
}
__device__ __forceinline__ void cp16(uint32_t saddr, const void* g) {
    asm volatile("cp.async.ca.shared.global [%0], [%1], 16;" :: "r"(saddr), "l"(g));
}
__device__ __forceinline__ void cp_commit() {
    asm volatile("cp.async.commit_group;" ::: "memory");
}
template <int N>
__device__ __forceinline__ void cp_wait() {
    asm volatile("cp.async.wait_group %0;" :: "n"(N) : "memory");
}
__device__ __forceinline__ void ldsm_x4(uint32_t* r, uint32_t addr) {
    asm volatile("ldmatrix.sync.aligned.m8n8.x4.shared.b16 {%0,%1,%2,%3}, [%4];"
                 : "=r"(r[0]), "=r"(r[1]), "=r"(r[2]), "=r"(r[3]) : "r"(addr));
}
__device__ __forceinline__ void mma16816h(float* c, const uint32_t* a, const uint32_t* b) {
    asm volatile(
        "mma.sync.aligned.m16n8k16.row.col.f32.f16.f16.f32 "
        "{%0,%1,%2,%3}, {%4,%5,%6,%7}, {%8,%9}, {%0,%1,%2,%3};"
        : "+f"(c[0]), "+f"(c[1]), "+f"(c[2]), "+f"(c[3])
        : "r"(a[0]), "r"(a[1]), "r"(a[2]), "r"(a[3]), "r"(b[0]), "r"(b[1]));
}

// ---------------- fused prep: feat->fp16 + edge hist + W transpose ----------------
// blocks [0, 5000): feature convert + hist; blocks [5000, 5768): 32x32 W-transpose tiles
#define PREP_FEAT_BLOCKS 5000                      // 5000*256 == N_NODES*VEC4
#define PREP_WT_BLOCKS   (16 * 16 * N_HOPS)        // 768
__global__ void prep_kernel(const float* __restrict__ feat, const float* __restrict__ W,
                            const int* __restrict__ dst) {
    __shared__ float tbuf[32][33];
    int b = blockIdx.x;
    if (b < PREP_FEAT_BLOCKS) {
        int i = b * 256 + threadIdx.x;
        float4 r = reinterpret_cast<const float4*>(feat)[i];
        reinterpret_cast<__half2*>(g_f16)[i * 2 + 0] = __floats2half2_rn(r.x, r.y);
        reinterpret_cast<__half2*>(g_f16)[i * 2 + 1] = __floats2half2_rn(r.z, r.w);
        if (i < N_EDGES) atomicAdd(&g_counts[dst[i]], 1);
    } else {
        int id = b - PREP_FEAT_BLOCKS;
        int z = id >> 8;                  // 256 tiles per z
        int tile = id & 255;
        int k0 = (tile & 15) * 32, n0 = (tile >> 4) * 32;
        int tx = threadIdx.x & 31, ty = threadIdx.x >> 5;   // (32, 8)
        const float* Wz = W + (size_t)z * IN_DIM * OUT_DIM;
#pragma unroll
        for (int r = 0; r < 4; r++)
            tbuf[ty + 8 * r][tx] = Wz[(size_t)(k0 + ty + 8 * r) * OUT_DIM + n0 + tx];
        __syncthreads();
        __half* Wt = g_wt16 + (size_t)z * IN_DIM * OUT_DIM;
#pragma unroll
        for (int r = 0; r < 4; r++)
            Wt[(size_t)(n0 + ty + 8 * r) * IN_DIM + k0 + tx] = __float2half(tbuf[tx][ty + 8 * r]);
    }
}

// ---------------- CSR build ----------------
__global__ void scan_kernel() {
    const int T = 1024, PER = 10;
    __shared__ int warp_tot[32];
    int t = threadIdx.x;
    int lane = t & 31, wd = t >> 5;
    int local[PER];
    int s = 0;
#pragma unroll
    for (int j = 0; j < PER; j++) {
        int idx = t * PER + j;
        int c = (idx < N_NODES) ? g_counts[idx] : 0;
        local[j] = s; s += c;
    }
    int tot = s;
    int inc = s;
#pragma unroll
    for (int off = 1; off < 32; off <<= 1) {
        int v = __shfl_up_sync(0xFFFFFFFF, inc, off);
        if (lane >= off) inc += v;
    }
    if (lane == 31) warp_tot[wd] = inc;
    __syncthreads();
    if (wd == 0) {
        int iv = warp_tot[lane];
#pragma unroll
        for (int off = 1; off < 32; off <<= 1) {
            int u = __shfl_up_sync(0xFFFFFFFF, iv, off);
            if (lane >= off) iv += u;
        }
        warp_tot[lane] = iv;
    }
    __syncthreads();
    int base = (wd > 0 ? warp_tot[wd - 1] : 0) + (inc - tot);
#pragma unroll
    for (int j = 0; j < PER; j++) {
        int idx = t * PER + j;
        if (idx < N_NODES) {
            int v = base + local[j];
            g_row_ptr[idx] = v;
            g_cursor[idx]  = v;
        }
    }
    if (t == T - 1) g_row_ptr[N_NODES] = base + tot;
}

// scatter (4 edges per thread for MLP) + re-zero counts
__global__ void scatter_kernel(const int* __restrict__ src, const int* __restrict__ dst,
                               const float* __restrict__ w) {
    int i = blockIdx.x * blockDim.x + threadIdx.x;
    int d[4], sv[4];
    float wv[4];
    int n_e = 0;
#pragma unroll
    for (int q = 0; q < 4; q++) {
        int e = i * 4 + q;
        if (e < N_EDGES) {
            d[q]  = dst[e];
            sv[q] = src[e];
            wv[q] = w[e];
            n_e = q + 1;
        }
    }
    int p[4];
#pragma unroll
    for (int q = 0; q < 4; q++)
        if (q < n_e) p[q] = atomicAdd(&g_cursor[d[q]], 1);
#pragma unroll
    for (int q = 0; q < 4; q++)
        if (q < n_e) { g_csr_src[p[q]] = sv[q]; g_csr_w[p[q]] = wv[q]; }
    if (i < N_NODES) g_counts[i] = 0;
}

// ---------------- SpMM hop (fp16 gather, fp32 accumulate, fp16 store) ----------------
// 64 threads per node; thread t owns 8 halves (16B) at column t*8
__global__ __launch_bounds__(64) void spmm_kernel(const float* __restrict__ D_norm, int hop) {
    const __half* __restrict__ h_in  = (hop == 1) ? g_f16 : g_h1h;
    __half* __restrict__       h_out = (hop == 1) ? g_h1h : g_h2h;
    int n = blockIdx.x;
    int t = threadIdx.x;   // 0..63
    int beg = g_row_ptr[n];
    int end = g_row_ptr[n + 1];
    float d = D_norm[n];

    __shared__ int2 s_ew[64];   // (src, w bits)

    float acc[8];
#pragma unroll
    for (int q = 0; q < 8; q++) acc[q] = 0.f;

    int deg = end - beg;
    if (deg <= 64) {
        // fast path (avg degree ~16): one fill, one sync, deep-unrolled loop
        if (t < deg)
            s_ew[t] = make_int2(g_csr_src[beg + t], __float_as_int(g_csr_w[beg + t]));
        __syncthreads();
#pragma unroll 4
        for (int i = 0; i < deg; i++) {
            int2 ew = s_ew[i];
            uint4 raw = reinterpret_cast<const uint4*>(h_in + (size_t)ew.x * IN_DIM)[t];
            float w = __int_as_float(ew.y);
            const __half2* ph = reinterpret_cast<const __half2*>(&raw);
#pragma unroll
            for (int q = 0; q < 4; q++) {
                float2 f = __half22float2(ph[q]);
                acc[2 * q + 0] += f.x * w;
                acc[2 * q + 1] += f.y * w;
            }
        }
    } else {
        for (int base = beg; base < end; base += 64) {
            int cnt = min(64, end - base);
            if (t < cnt)
                s_ew[t] = make_int2(g_csr_src[base + t], __float_as_int(g_csr_w[base + t]));
            __syncthreads();
#pragma unroll 4
            for (int i = 0; i < cnt; i++) {
                int2 ew = s_ew[i];
                uint4 raw = reinterpret_cast<const uint4*>(h_in + (size_t)ew.x * IN_DIM)[t];
                float w = __int_as_float(ew.y);
                const __half2* ph = reinterpret_cast<const __half2*>(&raw);
#pragma unroll
                for (int q = 0; q < 4; q++) {
                    float2 f = __half22float2(ph[q]);
                    acc[2 * q + 0] += f.x * w;
                    acc[2 * q + 1] += f.y * w;
                }
            }
            __syncthreads();
        }
    }
    __half2 o[4];
#pragma unroll
    for (int q = 0; q < 4; q++)
        o[q] = __floats2half2_rn(acc[2 * q] * d, acc[2 * q + 1] * d);
    reinterpret_cast<uint4*>(h_out + (size_t)n * IN_DIM)[t] = *reinterpret_cast<uint4*>(o);
}

// ---------------- fp16 mma GEMM + bias + relu, BK=64, 3-stage cp.async pipeline ----------------
// Row = 128B data + 16B pad = 144B (9 granules; 9 mod 8 = 1 -> conflict-free ldmatrix)
#define TROW_B    144
#define TILE_B    (128 * TROW_B)     // 18432
#define STAGE_B   (2 * TILE_B)       // 36864: A, B
#define KCHUNKS   8                  // 512 / 64
#define NSTAGE    3
#define GEMM_SMEM (NSTAGE * STAGE_B) // 110592

__global__ void __launch_bounds__(256, 2) gemm_mma_kernel(const float* __restrict__ bias,
                                                          float* __restrict__ out) {
    extern __shared__ char sm[];

    const int tid = threadIdx.x;
    const int wid = tid >> 5, lane = tid & 31;
    const int warp_m = wid & 1, warp_n = wid >> 1;
    const int nt = blockIdx.x, mt = blockIdx.y, z = blockIdx.z;
    const int m_base = mt * 128, n_base = nt * 128;

    const __half* A = (z == 0) ? g_f16 : (z == 1) ? g_h1h : g_h2h;
    const __half* B = g_wt16 + (size_t)z * IN_DIM * OUT_DIM;

    const uint32_t s_base = smem_u32(sm);

    // 1024 16B-chunks per tile (128 rows x 8), 256 threads -> 4 chunks each per tile
    const int rr[4] = { tid >> 3, (tid + 256) >> 3, (tid + 512) >> 3, (tid + 768) >> 3 };
    const int jj[4] = { tid & 7, (tid + 256) & 7, (tid + 512) & 7, (tid + 768) & 7 };
    int amr[4], bnr[4];
#pragma unroll
    for (int q = 0; q < 4; q++) {
        amr[q] = min(m_base + rr[q], N_NODES - 1);
        bnr[q] = n_base + rr[q];
    }

    auto issue_stage = [&](int s, int kc) {
        uint32_t st = s_base + s * STAGE_B;
        int kh = kc * 64;   // halves
#pragma unroll
        for (int q = 0; q < 4; q++) {
            cp16(st + 0 * TILE_B + rr[q] * TROW_B + jj[q] * 16, A + (size_t)amr[q] * IN_DIM + kh + jj[q] * 8);
            cp16(st + 1 * TILE_B + rr[q] * TROW_B + jj[q] * 16, B + (size_t)bnr[q] * IN_DIM + kh + jj[q] * 8);
        }
    };

    float acc[4][4][4];
#pragma unroll
    for (int i = 0; i < 4; i++)
#pragma unroll
        for (int j = 0; j < 4; j++)
#pragma unroll
            for (int q = 0; q < 4; q++) acc[i][j][q] = 0.f;

    const int a_row = warp_m * 64 + (lane & 15);
    const int a_kb  = (lane >> 4) * 16;
    const int b_row = warp_n * 32 + (lane & 7) + ((lane >> 4) << 3);
    const int b_kb  = ((lane >> 3) & 1) * 16;

    issue_stage(0, 0); cp_commit();
    issue_stage(1, 1); cp_commit();

    int stage = 0;
    for (int kc = 0; kc < KCHUNKS; kc++) {
        cp_wait<1>();
        __syncthreads();

        if (kc + 2 < KCHUNKS) {
            int s2 = stage + 2; if (s2 >= NSTAGE) s2 -= NSTAGE;
            issue_stage(s2, kc + 2);
        }
        cp_commit();   // possibly-empty group keeps wait<1> semantics uniform

        uint32_t st = s_base + stage * STAGE_B;
#pragma unroll
        for (int kk = 0; kk < 4; kk++) {
            int kb = kk * 32;   // 16 halves
            uint32_t af[4][4];
#pragma unroll
            for (int i = 0; i < 4; i++)
                ldsm_x4(af[i], st + 0 * TILE_B + (a_row + i * 16) * TROW_B + a_kb + kb);
            uint32_t bf[4][2];
#pragma unroll
            for (int jp = 0; jp < 2; jp++) {
                uint32_t r[4];
                ldsm_x4(r, st + 1 * TILE_B + (b_row + jp * 16) * TROW_B + b_kb + kb);
                bf[jp * 2][0] = r[0];     bf[jp * 2][1] = r[1];
                bf[jp * 2 + 1][0] = r[2]; bf[jp * 2 + 1][1] = r[3];
            }
#pragma unroll
            for (int i = 0; i < 4; i++)
#pragma unroll
                for (int j = 0; j < 4; j++)
                    mma16816h(acc[i][j], af[i], bf[j]);
        }
        if (++stage >= NSTAGE) stage = 0;
    }

    const float* bz = bias + z * OUT_DIM;
#pragma unroll
    for (int i = 0; i < 4; i++) {
        int row0 = m_base + warp_m * 64 + i * 16 + (lane >> 2);
#pragma unroll
        for (int j = 0; j < 4; j++) {
            int col = n_base + warp_n * 32 + j * 8 + (lane & 3) * 2;
            float b0 = bz[col], b1 = bz[col + 1];
            if (row0 < N_NODES) {
                float2 v;
                v.x = fmaxf(acc[i][j][0] + b0, 0.f);
                v.y = fmaxf(acc[i][j][1] + b1, 0.f);
                *(float2*)(out + (size_t)row0 * LDC + z * OUT_DIM + col) = v;
            }
            int row1 = row0 + 8;
            if (row1 < N_NODES) {
                float2 v;
                v.x = fmaxf(acc[i][j][2] + b0, 0.f);
                v.y = fmaxf(acc[i][j][3] + b1, 0.f);
                *(float2*)(out + (size_t)row1 * LDC + z * OUT_DIM + col) = v;
            }
        }
    }
}

// ---------------- launch ----------------
extern "C" void kernel_launch(void* const* d_in, const int* in_sizes, int n_in,
                              void* d_out, int out_size) {
    const float* features = (const float*)d_in[0];
    const float* D_norm   = (const float*)d_in[1];
    const float* edge_w   = (const float*)d_in[2];
    const float* W        = (const float*)d_in[3];
    const float* b        = (const float*)d_in[4];
    const int*   src      = (const int*)d_in[5];
    const int*   dst      = (const int*)d_in[6];
    float* out = (float*)d_out;

    static_assert(GEMM_SMEM <= 113 * 1024, "smem for 2 CTA/SM");
    cudaFuncSetAttribute(gemm_mma_kernel, cudaFuncAttributeMaxDynamicSharedMemorySize, GEMM_SMEM);

    // serial chain, single merged GEMM launch (verified best structure)
    prep_kernel<<<PREP_FEAT_BLOCKS + PREP_WT_BLOCKS, 256>>>(features, W, dst);   // 1
    scan_kernel<<<1, 1024>>>();                                                  // 2
    scatter_kernel<<<(N_EDGES / 4 + 255) / 256, 256>>>(src, dst, edge_w);        // 3
    spmm_kernel<<<N_NODES, 64>>>(D_norm, 1);                                     // 4
    spmm_kernel<<<N_NODES, 64>>>(D_norm, 2);                                     // 5
    dim3 ggrid(OUT_DIM / 128, (N_NODES + 127) / 128, N_HOPS);
    gemm_mma_kernel<<<ggrid, 256, GEMM_SMEM>>>(b, out);                          // 6
}